// round 1
// baseline (speedup 1.0000x reference)
#include <cuda_runtime.h>
#include <cstddef>

#define SEQS 8
#define SLEN 1024
#define DMODEL 768
#define NHEADS 12
#define DHEAD 64
#define IGNORE_VAL -100000.0f

// Scratch (device globals — no allocations allowed)
__device__ float g_Q[SEQS * NHEADS * SLEN * DHEAD];   // [seq][n][s][h]
__device__ float g_K[SEQS * NHEADS * SLEN * DHEAD];
__device__ float g_V[SEQS * NHEADS * SLEN * DHEAD];
__device__ float g_Z[SEQS * SLEN * DMODEL];           // [seq][s][n*64+h]

// ---------------------------------------------------------------------------
// Kernel 1: QKV projection.  grid = (128 token-tiles, 36 = type*12+head)
// Each block: 64 tokens x 64 dims (one head, one of Q/K/V), K=768 in chunks of 16.
// ---------------------------------------------------------------------------
__global__ __launch_bounds__(256) void qkv_kernel(
    const float* __restrict__ x0, const float* __restrict__ x1,
    const float* __restrict__ WQ, const float* __restrict__ bQ,
    const float* __restrict__ WK, const float* __restrict__ bK,
    const float* __restrict__ WV, const float* __restrict__ bV)
{
    __shared__ float As[64][17];
    __shared__ float Bs[16][64];

    const int tid = threadIdx.x;
    const int tt  = blockIdx.x;          // 0..127
    const int seq = tt >> 4;
    const int s0  = (tt & 15) << 6;
    const int typ = blockIdx.y / 12;
    const int n   = blockIdx.y - typ * 12;

    const float* W;
    const float* bias;
    float* out;
    if (typ == 0)      { W = WQ; bias = bQ; out = g_Q; }
    else if (typ == 1) { W = WK; bias = bK; out = g_K; }
    else               { W = WV; bias = bV; out = g_V; }

    const int b = seq >> 1, p = seq & 1;
    const float* X  = (p == 0 ? x0 : x1) + ((size_t)b * SLEN + s0) * DMODEL;
    const float* Wn = W + (size_t)n * DMODEL * DHEAD;

    const int row0 = (tid >> 4) << 2;
    const int col0 = (tid & 15) << 2;
    const int alr = tid >> 2, alc = (tid & 3) << 2;
    const int blr = tid >> 4, blc = (tid & 15) << 2;

    float acc[4][4];
#pragma unroll
    for (int i = 0; i < 4; i++)
#pragma unroll
        for (int j = 0; j < 4; j++) acc[i][j] = 0.f;

    for (int k0 = 0; k0 < DMODEL; k0 += 16) {
        float4 av = *(const float4*)(X + (size_t)alr * DMODEL + k0 + alc);
        As[alr][alc + 0] = av.x; As[alr][alc + 1] = av.y;
        As[alr][alc + 2] = av.z; As[alr][alc + 3] = av.w;
        float4 bv = *(const float4*)(Wn + (size_t)(k0 + blr) * DHEAD + blc);
        *(float4*)&Bs[blr][blc] = bv;
        __syncthreads();
#pragma unroll
        for (int kk = 0; kk < 16; kk++) {
            float a0 = As[row0 + 0][kk], a1 = As[row0 + 1][kk];
            float a2 = As[row0 + 2][kk], a3 = As[row0 + 3][kk];
            float4 b4 = *(float4*)&Bs[kk][col0];
            acc[0][0] += a0 * b4.x; acc[0][1] += a0 * b4.y; acc[0][2] += a0 * b4.z; acc[0][3] += a0 * b4.w;
            acc[1][0] += a1 * b4.x; acc[1][1] += a1 * b4.y; acc[1][2] += a1 * b4.z; acc[1][3] += a1 * b4.w;
            acc[2][0] += a2 * b4.x; acc[2][1] += a2 * b4.y; acc[2][2] += a2 * b4.z; acc[2][3] += a2 * b4.w;
            acc[3][0] += a3 * b4.x; acc[3][1] += a3 * b4.y; acc[3][2] += a3 * b4.z; acc[3][3] += a3 * b4.w;
        }
        __syncthreads();
    }

    float4 bb = *(const float4*)(bias + n * DHEAD + col0);
    size_t obase = (((size_t)seq * NHEADS + n) * SLEN + s0 + row0) * DHEAD + col0;
#pragma unroll
    for (int i = 0; i < 4; i++) {
        float4 v;
        v.x = acc[i][0] + bb.x; v.y = acc[i][1] + bb.y;
        v.z = acc[i][2] + bb.z; v.w = acc[i][3] + bb.w;
        *(float4*)(out + obase + (size_t)i * DHEAD) = v;
    }
}

// ---------------------------------------------------------------------------
// Kernel 2: causal attention (flash-style, online softmax).
// grid = (16 q-tiles, 96 = seq*12+head), 256 threads, 64x64 tiles.
// Thread layout: 16x16, 4x4 micro-tile (4 query rows x 4 dims/cols).
// ---------------------------------------------------------------------------
__global__ __launch_bounds__(256) void attn_kernel()
{
    extern __shared__ float sm[];
    float* Qs = sm;                 // 64 x 65
    float* Ks = sm + 64 * 65;       // 64 x 65
    float* Vs = Ks + 64 * 65;       // 64 x 68 (16B-aligned rows for float4)
    float* Ps = Vs + 64 * 68;       // 64 x 65

    const int tid = threadIdx.x;
    const int qb  = blockIdx.x;     // 0..15
    const int hn  = blockIdx.y;     // 0..95
    const int seq = hn / 12, n = hn - (hn / 12) * 12;

    const float* Qg = g_Q + (((size_t)seq * NHEADS + n) * SLEN + (size_t)qb * 64) * DHEAD;
    const float* Kg = g_K + (((size_t)seq * NHEADS + n) * SLEN) * DHEAD;
    const float* Vg = g_V + (((size_t)seq * NHEADS + n) * SLEN) * DHEAD;

    // load Q tile (64x64)
#pragma unroll
    for (int it = 0; it < 4; it++) {
        int idx = it * 256 + tid;
        int r = idx >> 4, c = (idx & 15) << 2;
        float4 v = *(const float4*)(Qg + (size_t)r * DHEAD + c);
        Qs[r * 65 + c + 0] = v.x; Qs[r * 65 + c + 1] = v.y;
        Qs[r * 65 + c + 2] = v.z; Qs[r * 65 + c + 3] = v.w;
    }

    const int ty = tid >> 4, tx = tid & 15;
    const int r0 = ty << 2;   // query rows owned
    const int c0 = tx << 2;   // cols owned (scores: key cols; output: head dims)

    float m[4], l[4], o[4][4];
#pragma unroll
    for (int i = 0; i < 4; i++) {
        m[i] = -1e30f; l[i] = 0.f;
#pragma unroll
        for (int j = 0; j < 4; j++) o[i][j] = 0.f;
    }

    for (int kb = 0; kb <= qb; kb++) {
        __syncthreads();   // previous PV done reading Vs/Ps; also covers Q load on iter 0
#pragma unroll
        for (int it = 0; it < 4; it++) {
            int idx = it * 256 + tid;
            int r = idx >> 4, c = (idx & 15) << 2;
            float4 kv = *(const float4*)(Kg + ((size_t)kb * 64 + r) * DHEAD + c);
            Ks[r * 65 + c + 0] = kv.x; Ks[r * 65 + c + 1] = kv.y;
            Ks[r * 65 + c + 2] = kv.z; Ks[r * 65 + c + 3] = kv.w;
            float4 vv = *(const float4*)(Vg + ((size_t)kb * 64 + r) * DHEAD + c);
            *(float4*)&Vs[r * 68 + c] = vv;
        }
        __syncthreads();

        // scores: 4x4 micro-tile, inner product over 64
        float sc[4][4];
#pragma unroll
        for (int i = 0; i < 4; i++)
#pragma unroll
            for (int j = 0; j < 4; j++) sc[i][j] = 0.f;
#pragma unroll 16
        for (int h = 0; h < 64; h++) {
            float a0 = Qs[(r0 + 0) * 65 + h], a1 = Qs[(r0 + 1) * 65 + h];
            float a2 = Qs[(r0 + 2) * 65 + h], a3 = Qs[(r0 + 3) * 65 + h];
            float b0 = Ks[(c0 + 0) * 65 + h], b1 = Ks[(c0 + 1) * 65 + h];
            float b2 = Ks[(c0 + 2) * 65 + h], b3 = Ks[(c0 + 3) * 65 + h];
            sc[0][0] += a0 * b0; sc[0][1] += a0 * b1; sc[0][2] += a0 * b2; sc[0][3] += a0 * b3;
            sc[1][0] += a1 * b0; sc[1][1] += a1 * b1; sc[1][2] += a1 * b2; sc[1][3] += a1 * b3;
            sc[2][0] += a2 * b0; sc[2][1] += a2 * b1; sc[2][2] += a2 * b2; sc[2][3] += a2 * b3;
            sc[3][0] += a3 * b0; sc[3][1] += a3 * b1; sc[3][2] += a3 * b2; sc[3][3] += a3 * b3;
        }

        const int qbase = qb * 64 + r0;
        const int cbase = kb * 64 + c0;
#pragma unroll
        for (int i = 0; i < 4; i++)
#pragma unroll
            for (int j = 0; j < 4; j++) {
                float v = sc[i][j] * 0.125f;
                sc[i][j] = (cbase + j > qbase + i) ? IGNORE_VAL : v;
            }

        // row max across the 16 tx-lanes
        float rmax[4];
#pragma unroll
        for (int i = 0; i < 4; i++)
            rmax[i] = fmaxf(fmaxf(sc[i][0], sc[i][1]), fmaxf(sc[i][2], sc[i][3]));
#pragma unroll
        for (int off = 1; off < 16; off <<= 1)
#pragma unroll
            for (int i = 0; i < 4; i++)
                rmax[i] = fmaxf(rmax[i], __shfl_xor_sync(0xffffffffu, rmax[i], off));

        float corr[4];
#pragma unroll
        for (int i = 0; i < 4; i++) {
            float nm = fmaxf(m[i], rmax[i]);
            corr[i] = __expf(m[i] - nm);
            m[i] = nm;
        }

        float rsum[4];
#pragma unroll
        for (int i = 0; i < 4; i++) {
            rsum[i] = 0.f;
#pragma unroll
            for (int j = 0; j < 4; j++) {
                float pv = __expf(sc[i][j] - m[i]);
                Ps[(r0 + i) * 65 + c0 + j] = pv;
                rsum[i] += pv;
            }
        }
#pragma unroll
        for (int off = 1; off < 16; off <<= 1)
#pragma unroll
            for (int i = 0; i < 4; i++)
                rsum[i] += __shfl_xor_sync(0xffffffffu, rsum[i], off);

#pragma unroll
        for (int i = 0; i < 4; i++) {
            l[i] = l[i] * corr[i] + rsum[i];
#pragma unroll
            for (int j = 0; j < 4; j++) o[i][j] *= corr[i];
        }
        __syncthreads();   // Ps visible to all

        // PV: o += P(64x64) @ V(64x64), 4x4 micro-tile
#pragma unroll 16
        for (int kk = 0; kk < 64; kk++) {
            float p0 = Ps[(r0 + 0) * 65 + kk], p1 = Ps[(r0 + 1) * 65 + kk];
            float p2 = Ps[(r0 + 2) * 65 + kk], p3 = Ps[(r0 + 3) * 65 + kk];
            float4 v4 = *(float4*)&Vs[kk * 68 + c0];
            o[0][0] += p0 * v4.x; o[0][1] += p0 * v4.y; o[0][2] += p0 * v4.z; o[0][3] += p0 * v4.w;
            o[1][0] += p1 * v4.x; o[1][1] += p1 * v4.y; o[1][2] += p1 * v4.z; o[1][3] += p1 * v4.w;
            o[2][0] += p2 * v4.x; o[2][1] += p2 * v4.y; o[2][2] += p2 * v4.z; o[2][3] += p2 * v4.w;
            o[3][0] += p3 * v4.x; o[3][1] += p3 * v4.y; o[3][2] += p3 * v4.z; o[3][3] += p3 * v4.w;
        }
    }

    // finalize and write Z[seq][s][n*64 + h]
    size_t zbase = ((size_t)seq * SLEN + (size_t)qb * 64 + r0) * DMODEL + n * DHEAD + c0;
#pragma unroll
    for (int i = 0; i < 4; i++) {
        float inv = 1.f / l[i];
        float4 w;
        w.x = o[i][0] * inv; w.y = o[i][1] * inv;
        w.z = o[i][2] * inv; w.w = o[i][3] * inv;
        *(float4*)(g_Z + zbase + (size_t)i * DMODEL) = w;
    }
}

// ---------------------------------------------------------------------------
// Kernel 3a: out[:, 0:2] = Z @ W_O_flat(768x768) + b_O
// grid = (128 token-tiles, 12 d-tiles)
// ---------------------------------------------------------------------------
__global__ __launch_bounds__(256) void out01_kernel(
    const float* __restrict__ WO, const float* __restrict__ bO,
    float* __restrict__ out)
{
    __shared__ float As[64][17];
    __shared__ float Bs[16][64];

    const int tid = threadIdx.x;
    const int r0g = blockIdx.x << 6;   // token 0..8191
    const int c0g = blockIdx.y << 6;   // dmodel col
    const float* A = g_Z + (size_t)r0g * DMODEL;

    const int row0 = (tid >> 4) << 2;
    const int col0 = (tid & 15) << 2;
    const int alr = tid >> 2, alc = (tid & 3) << 2;
    const int blr = tid >> 4, blc = (tid & 15) << 2;

    float acc[4][4];
#pragma unroll
    for (int i = 0; i < 4; i++)
#pragma unroll
        for (int j = 0; j < 4; j++) acc[i][j] = 0.f;

    for (int k0 = 0; k0 < DMODEL; k0 += 16) {
        float4 av = *(const float4*)(A + (size_t)alr * DMODEL + k0 + alc);
        As[alr][alc + 0] = av.x; As[alr][alc + 1] = av.y;
        As[alr][alc + 2] = av.z; As[alr][alc + 3] = av.w;
        float4 bv = *(const float4*)(WO + (size_t)(k0 + blr) * DMODEL + c0g + blc);
        *(float4*)&Bs[blr][blc] = bv;
        __syncthreads();
#pragma unroll
        for (int kk = 0; kk < 16; kk++) {
            float a0 = As[row0 + 0][kk], a1 = As[row0 + 1][kk];
            float a2 = As[row0 + 2][kk], a3 = As[row0 + 3][kk];
            float4 b4 = *(float4*)&Bs[kk][col0];
            acc[0][0] += a0 * b4.x; acc[0][1] += a0 * b4.y; acc[0][2] += a0 * b4.z; acc[0][3] += a0 * b4.w;
            acc[1][0] += a1 * b4.x; acc[1][1] += a1 * b4.y; acc[1][2] += a1 * b4.z; acc[1][3] += a1 * b4.w;
            acc[2][0] += a2 * b4.x; acc[2][1] += a2 * b4.y; acc[2][2] += a2 * b4.z; acc[2][3] += a2 * b4.w;
            acc[3][0] += a3 * b4.x; acc[3][1] += a3 * b4.y; acc[3][2] += a3 * b4.z; acc[3][3] += a3 * b4.w;
        }
        __syncthreads();
    }

    float4 bb = *(const float4*)(bO + c0g + col0);
#pragma unroll
    for (int i = 0; i < 4; i++) {
        int r = r0g + row0 + i;
        int seq = r >> 10, s = r & 1023;
        int b = seq >> 1, p = seq & 1;
        size_t oidx = (((size_t)(b * 14 + p)) * SLEN + s) * DMODEL + c0g + col0;
        float4 v;
        v.x = acc[i][0] + bb.x; v.y = acc[i][1] + bb.y;
        v.z = acc[i][2] + bb.z; v.w = acc[i][3] + bb.w;
        *(float4*)(out + oidx) = v;
    }
}

// ---------------------------------------------------------------------------
// Kernel 3b: out[:, 2+k] = out[:, 1] + (Z_alt_k - Z_orig_k) @ W_O[k]
// grid = (12 d-tiles, 64 token-tiles over 4096 (b,s), 12 heads)
// ---------------------------------------------------------------------------
__global__ __launch_bounds__(256) void ablate_kernel(
    const float* __restrict__ WO, float* __restrict__ out)
{
    __shared__ float As[64][65];
    __shared__ float Bs[64][64];

    const int tid = threadIdx.x;
    const int k  = blockIdx.z;
    const int t0 = blockIdx.y << 6;    // token over 4096 (b,s)
    const int d0 = blockIdx.x << 6;
    const int b  = t0 >> 10;
    const int s0 = t0 & 1023;

    const float* Za = g_Z + ((size_t)(b * 2 + 0) * SLEN + s0) * DMODEL + k * DHEAD;
    const float* Zo = g_Z + ((size_t)(b * 2 + 1) * SLEN + s0) * DMODEL + k * DHEAD;
    const float* Wk = WO + (size_t)k * DHEAD * DMODEL + d0;

#pragma unroll
    for (int it = 0; it < 4; it++) {
        int idx = it * 256 + tid;
        int r = idx >> 4, c = (idx & 15) << 2;
        float4 a = *(const float4*)(Za + (size_t)r * DMODEL + c);
        float4 q = *(const float4*)(Zo + (size_t)r * DMODEL + c);
        As[r][c + 0] = a.x - q.x; As[r][c + 1] = a.y - q.y;
        As[r][c + 2] = a.z - q.z; As[r][c + 3] = a.w - q.w;
        float4 w = *(const float4*)(Wk + (size_t)r * DMODEL + c);
        *(float4*)&Bs[r][c] = w;
    }
    __syncthreads();

    const int row0 = (tid >> 4) << 2;
    const int col0 = (tid & 15) << 2;
    float acc[4][4];
#pragma unroll
    for (int i = 0; i < 4; i++)
#pragma unroll
        for (int j = 0; j < 4; j++) acc[i][j] = 0.f;

#pragma unroll 16
    for (int kk = 0; kk < 64; kk++) {
        float a0 = As[row0 + 0][kk], a1 = As[row0 + 1][kk];
        float a2 = As[row0 + 2][kk], a3 = As[row0 + 3][kk];
        float4 b4 = *(float4*)&Bs[kk][col0];
        acc[0][0] += a0 * b4.x; acc[0][1] += a0 * b4.y; acc[0][2] += a0 * b4.z; acc[0][3] += a0 * b4.w;
        acc[1][0] += a1 * b4.x; acc[1][1] += a1 * b4.y; acc[1][2] += a1 * b4.z; acc[1][3] += a1 * b4.w;
        acc[2][0] += a2 * b4.x; acc[2][1] += a2 * b4.y; acc[2][2] += a2 * b4.z; acc[2][3] += a2 * b4.w;
        acc[3][0] += a3 * b4.x; acc[3][1] += a3 * b4.y; acc[3][2] += a3 * b4.z; acc[3][3] += a3 * b4.w;
    }

#pragma unroll
    for (int i = 0; i < 4; i++) {
        int s = s0 + row0 + i;
        size_t base1 = (((size_t)(b * 14 + 1)) * SLEN + s) * DMODEL + d0 + col0;
        size_t basek = (((size_t)(b * 14 + 2 + k)) * SLEN + s) * DMODEL + d0 + col0;
        float4 base = *(const float4*)(out + base1);
        float4 v;
        v.x = acc[i][0] + base.x; v.y = acc[i][1] + base.y;
        v.z = acc[i][2] + base.z; v.w = acc[i][3] + base.w;
        *(float4*)(out + basek) = v;
    }
}

// ---------------------------------------------------------------------------

extern "C" void kernel_launch(void* const* d_in, const int* in_sizes, int n_in,
                              void* d_out, int out_size)
{
    const float* x0 = (const float*)d_in[0];  // normalized_resid_pre (4,1,1024,768)
    const float* x1 = (const float*)d_in[1];  // alt_normalized_resid_pre (4,1024,768)
    const float* WQ = (const float*)d_in[2];
    const float* bQ = (const float*)d_in[3];
    const float* WK = (const float*)d_in[4];
    const float* bK = (const float*)d_in[5];
    const float* WV = (const float*)d_in[6];
    const float* bV = (const float*)d_in[7];
    const float* WO = (const float*)d_in[8];
    const float* bO = (const float*)d_in[9];
    float* out = (float*)d_out;

    qkv_kernel<<<dim3(128, 36), 256>>>(x0, x1, WQ, bQ, WK, bK, WV, bV);

    int smem = (64 * 65 * 3 + 64 * 68) * (int)sizeof(float);  // 67,328 B
    cudaFuncSetAttribute(attn_kernel, cudaFuncAttributeMaxDynamicSharedMemorySize, smem);
    attn_kernel<<<dim3(16, 96), 256, smem>>>();

    out01_kernel<<<dim3(128, 12), 256>>>(WO, bO, out);
    ablate_kernel<<<dim3(12, 64, 12), 256>>>(WO, out);
}

// round 2
// speedup vs baseline: 1.7896x; 1.7896x over previous
#include <cuda_runtime.h>
#include <cuda_bf16.h>
#include <cstdint>
#include <cstddef>

#define SEQS 8
#define SLEN 1024
#define DMODEL 768
#define NHEADS 12
#define DHEAD 64
#define IGNORE_VAL -100000.0f
#define PAD 72   // bf16 elements per smem row (144B) -> conflict-free ldmatrix

// Scratch (device globals — no allocations allowed)
__device__ float g_Q[SEQS * NHEADS * SLEN * DHEAD];   // [seq][n][s][h]
__device__ float g_K[SEQS * NHEADS * SLEN * DHEAD];
__device__ float g_V[SEQS * NHEADS * SLEN * DHEAD];
__device__ float g_Z[SEQS * SLEN * DMODEL];           // [seq][s][n*64+h]

// ---------------------------------------------------------------------------
// mma.sync helpers (bf16, fp32 accumulate)
// ---------------------------------------------------------------------------
__device__ __forceinline__ uint32_t sptr(const void* p) {
    return (uint32_t)__cvta_generic_to_shared(p);
}

__device__ __forceinline__ void ldsm_x4(uint32_t* r, uint32_t addr) {
    asm volatile("ldmatrix.sync.aligned.m8n8.x4.shared.b16 {%0,%1,%2,%3}, [%4];"
                 : "=r"(r[0]), "=r"(r[1]), "=r"(r[2]), "=r"(r[3]) : "r"(addr));
}
__device__ __forceinline__ void ldsm_x2t(uint32_t* r, uint32_t addr) {
    asm volatile("ldmatrix.sync.aligned.m8n8.x2.trans.shared.b16 {%0,%1}, [%2];"
                 : "=r"(r[0]), "=r"(r[1]) : "r"(addr));
}
__device__ __forceinline__ void mma_bf16(float* c, const uint32_t* a, const uint32_t* b) {
    asm volatile(
        "mma.sync.aligned.m16n8k16.row.col.f32.bf16.bf16.f32 "
        "{%0,%1,%2,%3}, {%4,%5,%6,%7}, {%8,%9}, {%0,%1,%2,%3};"
        : "+f"(c[0]), "+f"(c[1]), "+f"(c[2]), "+f"(c[3])
        : "r"(a[0]), "r"(a[1]), "r"(a[2]), "r"(a[3]), "r"(b[0]), "r"(b[1]));
}

__device__ __forceinline__ void split2(float f, __nv_bfloat16& h, __nv_bfloat16& l) {
    h = __float2bfloat16(f);
    l = __float2bfloat16(f - __bfloat162float(h));
}

// Shared inner machinery: per-k16-step fragment load + 3-pass mma.
// Ah/Al: [128][PAD], Bh/Bl: [64][PAD]
__device__ __forceinline__ void mma_step(
    const __nv_bfloat16* Ah, const __nv_bfloat16* Al,
    const __nv_bfloat16* Bh, const __nv_bfloat16* Bl,
    int ks, int m_w, int n_w, int lane, float acc[2][4][4])
{
    uint32_t ah[2][4], al[2][4], bh[4][2], bl[4][2];
    int ar = m_w + (lane & 15);
    int ac = ks + ((lane >> 4) << 3);
    ldsm_x4(ah[0], sptr(Ah + ar * PAD + ac));
    ldsm_x4(ah[1], sptr(Ah + (ar + 16) * PAD + ac));
    ldsm_x4(al[0], sptr(Al + ar * PAD + ac));
    ldsm_x4(al[1], sptr(Al + (ar + 16) * PAD + ac));
    int br = ks + (lane & 15);
#pragma unroll
    for (int f = 0; f < 4; f++) {
        ldsm_x2t(bh[f], sptr(Bh + br * PAD + n_w + f * 8));
        ldsm_x2t(bl[f], sptr(Bl + br * PAD + n_w + f * 8));
    }
#pragma unroll
    for (int mi = 0; mi < 2; mi++)
#pragma unroll
        for (int ni = 0; ni < 4; ni++) {
            mma_bf16(acc[mi][ni], ah[mi], bh[ni]);
            mma_bf16(acc[mi][ni], ah[mi], bl[ni]);
            mma_bf16(acc[mi][ni], al[mi], bh[ni]);
        }
}

// ---------------------------------------------------------------------------
// Kernel 1: QKV projection on tensor cores.
// grid = (64 token-tiles of 128, 36 = typ*12+head), 256 threads.
// C tile 128x64, warps 4(m) x 2(n), warp tile 32x32.
// ---------------------------------------------------------------------------
__global__ __launch_bounds__(256) void qkv_mma_kernel(
    const float* __restrict__ x0, const float* __restrict__ x1,
    const float* __restrict__ WQ, const float* __restrict__ bQ,
    const float* __restrict__ WK, const float* __restrict__ bK,
    const float* __restrict__ WV, const float* __restrict__ bV)
{
    extern __shared__ __nv_bfloat16 smem[];
    __nv_bfloat16* Ah = smem;
    __nv_bfloat16* Al = Ah + 128 * PAD;
    __nv_bfloat16* Bh = Al + 128 * PAD;
    __nv_bfloat16* Bl = Bh + 64 * PAD;

    const int tid = threadIdx.x, lane = tid & 31, warp = tid >> 5;
    const int mt = blockIdx.x;                 // 0..63
    const int seq = mt >> 3, s0 = (mt & 7) << 7;
    const int typ = blockIdx.y / NHEADS;
    const int n = blockIdx.y - typ * NHEADS;

    const float *W, *bias;
    float* outp;
    if (typ == 0)      { W = WQ; bias = bQ; outp = g_Q; }
    else if (typ == 1) { W = WK; bias = bK; outp = g_K; }
    else               { W = WV; bias = bV; outp = g_V; }

    const int b = seq >> 1, p = seq & 1;
    const float* X  = (p ? x1 : x0) + ((size_t)b * SLEN + s0) * DMODEL;
    const float* Wn = W + (size_t)n * DMODEL * DHEAD;

    const int m_w = (warp >> 1) << 5;
    const int n_w = (warp & 1) << 5;

    float acc[2][4][4];
#pragma unroll
    for (int mi = 0; mi < 2; mi++)
#pragma unroll
        for (int ni = 0; ni < 4; ni++)
#pragma unroll
            for (int j = 0; j < 4; j++) acc[mi][ni][j] = 0.f;

    for (int k0 = 0; k0 < DMODEL; k0 += 64) {
#pragma unroll
        for (int it = 0; it < 8; it++) {         // A 128x64
            int idx = it * 256 + tid;
            int r = idx >> 4, c = (idx & 15) << 2;
            float4 v = *(const float4*)(X + (size_t)r * DMODEL + k0 + c);
            __nv_bfloat16 h, l;
            split2(v.x, h, l); Ah[r * PAD + c + 0] = h; Al[r * PAD + c + 0] = l;
            split2(v.y, h, l); Ah[r * PAD + c + 1] = h; Al[r * PAD + c + 1] = l;
            split2(v.z, h, l); Ah[r * PAD + c + 2] = h; Al[r * PAD + c + 2] = l;
            split2(v.w, h, l); Ah[r * PAD + c + 3] = h; Al[r * PAD + c + 3] = l;
        }
#pragma unroll
        for (int it = 0; it < 4; it++) {         // B 64x64
            int idx = it * 256 + tid;
            int r = idx >> 4, c = (idx & 15) << 2;
            float4 v = *(const float4*)(Wn + (size_t)(k0 + r) * DHEAD + c);
            __nv_bfloat16 h, l;
            split2(v.x, h, l); Bh[r * PAD + c + 0] = h; Bl[r * PAD + c + 0] = l;
            split2(v.y, h, l); Bh[r * PAD + c + 1] = h; Bl[r * PAD + c + 1] = l;
            split2(v.z, h, l); Bh[r * PAD + c + 2] = h; Bl[r * PAD + c + 2] = l;
            split2(v.w, h, l); Bh[r * PAD + c + 3] = h; Bl[r * PAD + c + 3] = l;
        }
        __syncthreads();
#pragma unroll
        for (int ks = 0; ks < 64; ks += 16)
            mma_step(Ah, Al, Bh, Bl, ks, m_w, n_w, lane, acc);
        __syncthreads();
    }

#pragma unroll
    for (int mi = 0; mi < 2; mi++) {
        int row = m_w + mi * 16 + (lane >> 2);
#pragma unroll
        for (int ni = 0; ni < 4; ni++) {
            int col = n_w + ni * 8 + ((lane & 3) << 1);
            float b0 = bias[n * DHEAD + col], b1 = bias[n * DHEAD + col + 1];
            size_t o0 = (((size_t)seq * NHEADS + n) * SLEN + s0 + row) * DHEAD + col;
            float2 v0 = make_float2(acc[mi][ni][0] + b0, acc[mi][ni][1] + b1);
            *(float2*)(outp + o0) = v0;
            float2 v1 = make_float2(acc[mi][ni][2] + b0, acc[mi][ni][3] + b1);
            *(float2*)(outp + o0 + (size_t)8 * DHEAD) = v1;
        }
    }
}

// ---------------------------------------------------------------------------
// Kernel 2: causal attention (unchanged fp32 flash-style from R1).
// ---------------------------------------------------------------------------
__global__ __launch_bounds__(256) void attn_kernel()
{
    extern __shared__ float sm[];
    float* Qs = sm;                 // 64 x 65
    float* Ks = sm + 64 * 65;       // 64 x 65
    float* Vs = Ks + 64 * 65;       // 64 x 68
    float* Ps = Vs + 64 * 68;       // 64 x 65

    const int tid = threadIdx.x;
    const int qb  = blockIdx.x;
    const int hn  = blockIdx.y;
    const int seq = hn / 12, n = hn - (hn / 12) * 12;

    const float* Qg = g_Q + (((size_t)seq * NHEADS + n) * SLEN + (size_t)qb * 64) * DHEAD;
    const float* Kg = g_K + (((size_t)seq * NHEADS + n) * SLEN) * DHEAD;
    const float* Vg = g_V + (((size_t)seq * NHEADS + n) * SLEN) * DHEAD;

#pragma unroll
    for (int it = 0; it < 4; it++) {
        int idx = it * 256 + tid;
        int r = idx >> 4, c = (idx & 15) << 2;
        float4 v = *(const float4*)(Qg + (size_t)r * DHEAD + c);
        Qs[r * 65 + c + 0] = v.x; Qs[r * 65 + c + 1] = v.y;
        Qs[r * 65 + c + 2] = v.z; Qs[r * 65 + c + 3] = v.w;
    }

    const int ty = tid >> 4, tx = tid & 15;
    const int r0 = ty << 2;
    const int c0 = tx << 2;

    float m[4], l[4], o[4][4];
#pragma unroll
    for (int i = 0; i < 4; i++) {
        m[i] = -1e30f; l[i] = 0.f;
#pragma unroll
        for (int j = 0; j < 4; j++) o[i][j] = 0.f;
    }

    for (int kb = 0; kb <= qb; kb++) {
        __syncthreads();
#pragma unroll
        for (int it = 0; it < 4; it++) {
            int idx = it * 256 + tid;
            int r = idx >> 4, c = (idx & 15) << 2;
            float4 kv = *(const float4*)(Kg + ((size_t)kb * 64 + r) * DHEAD + c);
            Ks[r * 65 + c + 0] = kv.x; Ks[r * 65 + c + 1] = kv.y;
            Ks[r * 65 + c + 2] = kv.z; Ks[r * 65 + c + 3] = kv.w;
            float4 vv = *(const float4*)(Vg + ((size_t)kb * 64 + r) * DHEAD + c);
            *(float4*)&Vs[r * 68 + c] = vv;
        }
        __syncthreads();

        float sc[4][4];
#pragma unroll
        for (int i = 0; i < 4; i++)
#pragma unroll
            for (int j = 0; j < 4; j++) sc[i][j] = 0.f;
#pragma unroll 16
        for (int h = 0; h < 64; h++) {
            float a0 = Qs[(r0 + 0) * 65 + h], a1 = Qs[(r0 + 1) * 65 + h];
            float a2 = Qs[(r0 + 2) * 65 + h], a3 = Qs[(r0 + 3) * 65 + h];
            float b0 = Ks[(c0 + 0) * 65 + h], b1 = Ks[(c0 + 1) * 65 + h];
            float b2 = Ks[(c0 + 2) * 65 + h], b3 = Ks[(c0 + 3) * 65 + h];
            sc[0][0] += a0 * b0; sc[0][1] += a0 * b1; sc[0][2] += a0 * b2; sc[0][3] += a0 * b3;
            sc[1][0] += a1 * b0; sc[1][1] += a1 * b1; sc[1][2] += a1 * b2; sc[1][3] += a1 * b3;
            sc[2][0] += a2 * b0; sc[2][1] += a2 * b1; sc[2][2] += a2 * b2; sc[2][3] += a2 * b3;
            sc[3][0] += a3 * b0; sc[3][1] += a3 * b1; sc[3][2] += a3 * b2; sc[3][3] += a3 * b3;
        }

        const int qbase = qb * 64 + r0;
        const int cbase = kb * 64 + c0;
#pragma unroll
        for (int i = 0; i < 4; i++)
#pragma unroll
            for (int j = 0; j < 4; j++) {
                float v = sc[i][j] * 0.125f;
                sc[i][j] = (cbase + j > qbase + i) ? IGNORE_VAL : v;
            }

        float rmax[4];
#pragma unroll
        for (int i = 0; i < 4; i++)
            rmax[i] = fmaxf(fmaxf(sc[i][0], sc[i][1]), fmaxf(sc[i][2], sc[i][3]));
#pragma unroll
        for (int off = 1; off < 16; off <<= 1)
#pragma unroll
            for (int i = 0; i < 4; i++)
                rmax[i] = fmaxf(rmax[i], __shfl_xor_sync(0xffffffffu, rmax[i], off));

        float corr[4];
#pragma unroll
        for (int i = 0; i < 4; i++) {
            float nm = fmaxf(m[i], rmax[i]);
            corr[i] = __expf(m[i] - nm);
            m[i] = nm;
        }

        float rsum[4];
#pragma unroll
        for (int i = 0; i < 4; i++) {
            rsum[i] = 0.f;
#pragma unroll
            for (int j = 0; j < 4; j++) {
                float pv = __expf(sc[i][j] - m[i]);
                Ps[(r0 + i) * 65 + c0 + j] = pv;
                rsum[i] += pv;
            }
        }
#pragma unroll
        for (int off = 1; off < 16; off <<= 1)
#pragma unroll
            for (int i = 0; i < 4; i++)
                rsum[i] += __shfl_xor_sync(0xffffffffu, rsum[i], off);

#pragma unroll
        for (int i = 0; i < 4; i++) {
            l[i] = l[i] * corr[i] + rsum[i];
#pragma unroll
            for (int j = 0; j < 4; j++) o[i][j] *= corr[i];
        }
        __syncthreads();

#pragma unroll 16
        for (int kk = 0; kk < 64; kk++) {
            float p0 = Ps[(r0 + 0) * 65 + kk], p1 = Ps[(r0 + 1) * 65 + kk];
            float p2 = Ps[(r0 + 2) * 65 + kk], p3 = Ps[(r0 + 3) * 65 + kk];
            float4 v4 = *(float4*)&Vs[kk * 68 + c0];
            o[0][0] += p0 * v4.x; o[0][1] += p0 * v4.y; o[0][2] += p0 * v4.z; o[0][3] += p0 * v4.w;
            o[1][0] += p1 * v4.x; o[1][1] += p1 * v4.y; o[1][2] += p1 * v4.z; o[1][3] += p1 * v4.w;
            o[2][0] += p2 * v4.x; o[2][1] += p2 * v4.y; o[2][2] += p2 * v4.z; o[2][3] += p2 * v4.w;
            o[3][0] += p3 * v4.x; o[3][1] += p3 * v4.y; o[3][2] += p3 * v4.z; o[3][3] += p3 * v4.w;
        }
    }

    size_t zbase = ((size_t)seq * SLEN + (size_t)qb * 64 + r0) * DMODEL + n * DHEAD + c0;
#pragma unroll
    for (int i = 0; i < 4; i++) {
        float inv = 1.f / l[i];
        float4 w;
        w.x = o[i][0] * inv; w.y = o[i][1] * inv;
        w.z = o[i][2] * inv; w.w = o[i][3] * inv;
        *(float4*)(g_Z + zbase + (size_t)i * DMODEL) = w;
    }
}

// ---------------------------------------------------------------------------
// Kernel 3a: out[:, 0:2] = Z @ W_O_flat(768x768) + b_O  (tensor cores)
// grid = (64 token-tiles of 128, 12 d-tiles of 64)
// ---------------------------------------------------------------------------
__global__ __launch_bounds__(256) void out01_mma_kernel(
    const float* __restrict__ WO, const float* __restrict__ bO,
    float* __restrict__ out)
{
    extern __shared__ __nv_bfloat16 smem[];
    __nv_bfloat16* Ah = smem;
    __nv_bfloat16* Al = Ah + 128 * PAD;
    __nv_bfloat16* Bh = Al + 128 * PAD;
    __nv_bfloat16* Bl = Bh + 64 * PAD;

    const int tid = threadIdx.x, lane = tid & 31, warp = tid >> 5;
    const int r0g = blockIdx.x << 7;           // token 0..8191 (tile 128)
    const int c0g = blockIdx.y << 6;           // dmodel col (tile 64)
    const float* A = g_Z + (size_t)r0g * DMODEL;

    const int m_w = (warp >> 1) << 5;
    const int n_w = (warp & 1) << 5;

    float acc[2][4][4];
#pragma unroll
    for (int mi = 0; mi < 2; mi++)
#pragma unroll
        for (int ni = 0; ni < 4; ni++)
#pragma unroll
            for (int j = 0; j < 4; j++) acc[mi][ni][j] = 0.f;

    for (int k0 = 0; k0 < DMODEL; k0 += 64) {
#pragma unroll
        for (int it = 0; it < 8; it++) {
            int idx = it * 256 + tid;
            int r = idx >> 4, c = (idx & 15) << 2;
            float4 v = *(const float4*)(A + (size_t)r * DMODEL + k0 + c);
            __nv_bfloat16 h, l;
            split2(v.x, h, l); Ah[r * PAD + c + 0] = h; Al[r * PAD + c + 0] = l;
            split2(v.y, h, l); Ah[r * PAD + c + 1] = h; Al[r * PAD + c + 1] = l;
            split2(v.z, h, l); Ah[r * PAD + c + 2] = h; Al[r * PAD + c + 2] = l;
            split2(v.w, h, l); Ah[r * PAD + c + 3] = h; Al[r * PAD + c + 3] = l;
        }
#pragma unroll
        for (int it = 0; it < 4; it++) {
            int idx = it * 256 + tid;
            int r = idx >> 4, c = (idx & 15) << 2;
            float4 v = *(const float4*)(WO + (size_t)(k0 + r) * DMODEL + c0g + c);
            __nv_bfloat16 h, l;
            split2(v.x, h, l); Bh[r * PAD + c + 0] = h; Bl[r * PAD + c + 0] = l;
            split2(v.y, h, l); Bh[r * PAD + c + 1] = h; Bl[r * PAD + c + 1] = l;
            split2(v.z, h, l); Bh[r * PAD + c + 2] = h; Bl[r * PAD + c + 2] = l;
            split2(v.w, h, l); Bh[r * PAD + c + 3] = h; Bl[r * PAD + c + 3] = l;
        }
        __syncthreads();
#pragma unroll
        for (int ks = 0; ks < 64; ks += 16)
            mma_step(Ah, Al, Bh, Bl, ks, m_w, n_w, lane, acc);
        __syncthreads();
    }

#pragma unroll
    for (int mi = 0; mi < 2; mi++) {
        int rloc = m_w + mi * 16 + (lane >> 2);
#pragma unroll
        for (int ni = 0; ni < 4; ni++) {
            int col = n_w + ni * 8 + ((lane & 3) << 1);
            float b0 = bO[c0g + col], b1 = bO[c0g + col + 1];
#pragma unroll
            for (int half = 0; half < 2; half++) {
                int r = r0g + rloc + half * 8;
                int seq = r >> 10, s = r & 1023;
                int b = seq >> 1, p = seq & 1;
                size_t oidx = (((size_t)(b * 14 + p)) * SLEN + s) * DMODEL + c0g + col;
                float2 v = make_float2(acc[mi][ni][half * 2 + 0] + b0,
                                       acc[mi][ni][half * 2 + 1] + b1);
                *(float2*)(out + oidx) = v;
            }
        }
    }
}

// ---------------------------------------------------------------------------
// Kernel 3b: out[:, 2+k] = out[:, 1] + (Z_alt_k - Z_orig_k) @ W_O[k]
// grid = (12 d-tiles, 32 token-tiles of 128, 12 heads), K=64 single chunk.
// ---------------------------------------------------------------------------
__global__ __launch_bounds__(256) void ablate_mma_kernel(
    const float* __restrict__ WO, float* __restrict__ out)
{
    extern __shared__ __nv_bfloat16 smem[];
    __nv_bfloat16* Ah = smem;
    __nv_bfloat16* Al = Ah + 128 * PAD;
    __nv_bfloat16* Bh = Al + 128 * PAD;
    __nv_bfloat16* Bl = Bh + 64 * PAD;

    const int tid = threadIdx.x, lane = tid & 31, warp = tid >> 5;
    const int k  = blockIdx.z;
    const int t0 = blockIdx.y << 7;            // token over 4096 (b,s)
    const int d0 = blockIdx.x << 6;
    const int b  = t0 >> 10;
    const int s0 = t0 & 1023;

    const float* Za = g_Z + ((size_t)(b * 2 + 0) * SLEN + s0) * DMODEL + k * DHEAD;
    const float* Zo = g_Z + ((size_t)(b * 2 + 1) * SLEN + s0) * DMODEL + k * DHEAD;
    const float* Wk = WO + (size_t)k * DHEAD * DMODEL + d0;

    // A = Za - Zo (128 x 64)
#pragma unroll
    for (int it = 0; it < 8; it++) {
        int idx = it * 256 + tid;
        int r = idx >> 4, c = (idx & 15) << 2;
        float4 a = *(const float4*)(Za + (size_t)r * DMODEL + c);
        float4 q = *(const float4*)(Zo + (size_t)r * DMODEL + c);
        float d[4] = {a.x - q.x, a.y - q.y, a.z - q.z, a.w - q.w};
        __nv_bfloat16 h, l;
#pragma unroll
        for (int j = 0; j < 4; j++) {
            split2(d[j], h, l);
            Ah[r * PAD + c + j] = h; Al[r * PAD + c + j] = l;
        }
    }
    // B = Wk (64 x 64)
#pragma unroll
    for (int it = 0; it < 4; it++) {
        int idx = it * 256 + tid;
        int r = idx >> 4, c = (idx & 15) << 2;
        float4 v = *(const float4*)(Wk + (size_t)r * DMODEL + c);
        __nv_bfloat16 h, l;
        split2(v.x, h, l); Bh[r * PAD + c + 0] = h; Bl[r * PAD + c + 0] = l;
        split2(v.y, h, l); Bh[r * PAD + c + 1] = h; Bl[r * PAD + c + 1] = l;
        split2(v.z, h, l); Bh[r * PAD + c + 2] = h; Bl[r * PAD + c + 2] = l;
        split2(v.w, h, l); Bh[r * PAD + c + 3] = h; Bl[r * PAD + c + 3] = l;
    }
    __syncthreads();

    const int m_w = (warp >> 1) << 5;
    const int n_w = (warp & 1) << 5;

    float acc[2][4][4];
#pragma unroll
    for (int mi = 0; mi < 2; mi++)
#pragma unroll
        for (int ni = 0; ni < 4; ni++)
#pragma unroll
            for (int j = 0; j < 4; j++) acc[mi][ni][j] = 0.f;

#pragma unroll
    for (int ks = 0; ks < 64; ks += 16)
        mma_step(Ah, Al, Bh, Bl, ks, m_w, n_w, lane, acc);

#pragma unroll
    for (int mi = 0; mi < 2; mi++) {
        int rloc = m_w + mi * 16 + (lane >> 2);
#pragma unroll
        for (int ni = 0; ni < 4; ni++) {
            int col = n_w + ni * 8 + ((lane & 3) << 1);
#pragma unroll
            for (int half = 0; half < 2; half++) {
                int s = s0 + rloc + half * 8;
                size_t base1 = (((size_t)(b * 14 + 1)) * SLEN + s) * DMODEL + d0 + col;
                size_t basek = (((size_t)(b * 14 + 2 + k)) * SLEN + s) * DMODEL + d0 + col;
                float2 base = *(const float2*)(out + base1);
                float2 v = make_float2(acc[mi][ni][half * 2 + 0] + base.x,
                                       acc[mi][ni][half * 2 + 1] + base.y);
                *(float2*)(out + basek) = v;
            }
        }
    }
}

// ---------------------------------------------------------------------------

extern "C" void kernel_launch(void* const* d_in, const int* in_sizes, int n_in,
                              void* d_out, int out_size)
{
    const float* x0 = (const float*)d_in[0];
    const float* x1 = (const float*)d_in[1];
    const float* WQ = (const float*)d_in[2];
    const float* bQ = (const float*)d_in[3];
    const float* WK = (const float*)d_in[4];
    const float* bK = (const float*)d_in[5];
    const float* WV = (const float*)d_in[6];
    const float* bV = (const float*)d_in[7];
    const float* WO = (const float*)d_in[8];
    const float* bO = (const float*)d_in[9];
    float* out = (float*)d_out;

    const int gemm_smem = (128 * 2 + 64 * 2) * PAD * (int)sizeof(__nv_bfloat16); // 55296
    cudaFuncSetAttribute(qkv_mma_kernel, cudaFuncAttributeMaxDynamicSharedMemorySize, gemm_smem);
    cudaFuncSetAttribute(out01_mma_kernel, cudaFuncAttributeMaxDynamicSharedMemorySize, gemm_smem);
    cudaFuncSetAttribute(ablate_mma_kernel, cudaFuncAttributeMaxDynamicSharedMemorySize, gemm_smem);

    qkv_mma_kernel<<<dim3(64, 36), 256, gemm_smem>>>(x0, x1, WQ, bQ, WK, bK, WV, bV);

    int attn_smem = (64 * 65 * 3 + 64 * 68) * (int)sizeof(float);  // 67,328 B
    cudaFuncSetAttribute(attn_kernel, cudaFuncAttributeMaxDynamicSharedMemorySize, attn_smem);
    attn_kernel<<<dim3(16, 96), 256, attn_smem>>>();

    out01_mma_kernel<<<dim3(64, 12), 256, gemm_smem>>>(WO, bO, out);
    ablate_mma_kernel<<<dim3(12, 32, 12), 256, gemm_smem>>>(WO, out);
}

// round 5
// speedup vs baseline: 2.5348x; 1.4165x over previous
#include <cuda_runtime.h>
#include <cuda_bf16.h>
#include <cstdint>
#include <cstddef>

#define SEQS 8
#define SLEN 1024
#define DMODEL 768
#define NHEADS 12
#define DHEAD 64
#define PAD 72   // bf16 elements per smem row (144B)

// Scratch (device globals — no allocations allowed)
__device__ __nv_bfloat16 g_Qh[SEQS * NHEADS * SLEN * DHEAD];
__device__ __nv_bfloat16 g_Ql[SEQS * NHEADS * SLEN * DHEAD];
__device__ __nv_bfloat16 g_Kh[SEQS * NHEADS * SLEN * DHEAD];
__device__ __nv_bfloat16 g_Kl[SEQS * NHEADS * SLEN * DHEAD];
__device__ __nv_bfloat16 g_Vh[SEQS * NHEADS * SLEN * DHEAD];
__device__ __nv_bfloat16 g_Vl[SEQS * NHEADS * SLEN * DHEAD];
__device__ float g_Z[SEQS * SLEN * DMODEL];           // [seq][s][n*64+h]

// ---------------------------------------------------------------------------
// mma.sync helpers (bf16, fp32 accumulate)
// ---------------------------------------------------------------------------
__device__ __forceinline__ uint32_t sptr(const void* p) {
    return (uint32_t)__cvta_generic_to_shared(p);
}
__device__ __forceinline__ void ldsm_x4(uint32_t* r, uint32_t addr) {
    asm volatile("ldmatrix.sync.aligned.m8n8.x4.shared.b16 {%0,%1,%2,%3}, [%4];"
                 : "=r"(r[0]), "=r"(r[1]), "=r"(r[2]), "=r"(r[3]) : "r"(addr));
}
__device__ __forceinline__ void ldsm_x4t(uint32_t* r, uint32_t addr) {
    asm volatile("ldmatrix.sync.aligned.m8n8.x4.trans.shared.b16 {%0,%1,%2,%3}, [%4];"
                 : "=r"(r[0]), "=r"(r[1]), "=r"(r[2]), "=r"(r[3]) : "r"(addr));
}
__device__ __forceinline__ void ldsm_x2t(uint32_t* r, uint32_t addr) {
    asm volatile("ldmatrix.sync.aligned.m8n8.x2.trans.shared.b16 {%0,%1}, [%2];"
                 : "=r"(r[0]), "=r"(r[1]) : "r"(addr));
}
__device__ __forceinline__ void mma_bf16(float* c, const uint32_t* a, const uint32_t* b) {
    asm volatile(
        "mma.sync.aligned.m16n8k16.row.col.f32.bf16.bf16.f32 "
        "{%0,%1,%2,%3}, {%4,%5,%6,%7}, {%8,%9}, {%0,%1,%2,%3};"
        : "+f"(c[0]), "+f"(c[1]), "+f"(c[2]), "+f"(c[3])
        : "r"(a[0]), "r"(a[1]), "r"(a[2]), "r"(a[3]), "r"(b[0]), "r"(b[1]));
}
__device__ __forceinline__ void split2(float f, __nv_bfloat16& h, __nv_bfloat16& l) {
    h = __float2bfloat16(f);
    l = __float2bfloat16(f - __bfloat162float(h));
}
__device__ __forceinline__ float fast_exp2(float x) {
    float r;
    asm("ex2.approx.ftz.f32 %0, %1;" : "=f"(r) : "f"(x));
    return r;
}
__device__ __forceinline__ uint32_t packbf(float a, float b) {
    __nv_bfloat162 v = __floats2bfloat162_rn(a, b);
    return *(uint32_t*)&v;
}

// GEMM inner step (used by qkv/out01/ablate): Ah/Al [128][PAD], Bh/Bl [64][PAD]
__device__ __forceinline__ void mma_step(
    const __nv_bfloat16* Ah, const __nv_bfloat16* Al,
    const __nv_bfloat16* Bh, const __nv_bfloat16* Bl,
    int ks, int m_w, int n_w, int lane, float acc[2][4][4])
{
    uint32_t ah[2][4], al[2][4], bh[4][2], bl[4][2];
    int ar = m_w + (lane & 15);
    int ac = ks + ((lane >> 4) << 3);
    ldsm_x4(ah[0], sptr(Ah + ar * PAD + ac));
    ldsm_x4(ah[1], sptr(Ah + (ar + 16) * PAD + ac));
    ldsm_x4(al[0], sptr(Al + ar * PAD + ac));
    ldsm_x4(al[1], sptr(Al + (ar + 16) * PAD + ac));
    int br = ks + (lane & 15);
#pragma unroll
    for (int f = 0; f < 4; f++) {
        ldsm_x2t(bh[f], sptr(Bh + br * PAD + n_w + f * 8));
        ldsm_x2t(bl[f], sptr(Bl + br * PAD + n_w + f * 8));
    }
#pragma unroll
    for (int mi = 0; mi < 2; mi++)
#pragma unroll
        for (int ni = 0; ni < 4; ni++) {
            mma_bf16(acc[mi][ni], ah[mi], bh[ni]);
            mma_bf16(acc[mi][ni], ah[mi], bl[ni]);
            mma_bf16(acc[mi][ni], al[mi], bh[ni]);
        }
}

// ---------------------------------------------------------------------------
// Kernel 1: QKV projection on tensor cores; writes bf16 hi/lo pairs.
// grid = (64 token-tiles of 128, 36 = typ*12+head), 256 threads.
// ---------------------------------------------------------------------------
__global__ __launch_bounds__(256) void qkv_mma_kernel(
    const float* __restrict__ x0, const float* __restrict__ x1,
    const float* __restrict__ WQ, const float* __restrict__ bQ,
    const float* __restrict__ WK, const float* __restrict__ bK,
    const float* __restrict__ WV, const float* __restrict__ bV)
{
    extern __shared__ __nv_bfloat16 smem[];
    __nv_bfloat16* Ah = smem;
    __nv_bfloat16* Al = Ah + 128 * PAD;
    __nv_bfloat16* Bh = Al + 128 * PAD;
    __nv_bfloat16* Bl = Bh + 64 * PAD;

    const int tid = threadIdx.x, lane = tid & 31, warp = tid >> 5;
    const int mt = blockIdx.x;
    const int seq = mt >> 3, s0 = (mt & 7) << 7;
    const int typ = blockIdx.y / NHEADS;
    const int n = blockIdx.y - typ * NHEADS;

    const float *W, *bias;
    __nv_bfloat16 *outh, *outl;
    if (typ == 0)      { W = WQ; bias = bQ; outh = g_Qh; outl = g_Ql; }
    else if (typ == 1) { W = WK; bias = bK; outh = g_Kh; outl = g_Kl; }
    else               { W = WV; bias = bV; outh = g_Vh; outl = g_Vl; }

    const int b = seq >> 1, p = seq & 1;
    const float* X  = (p ? x1 : x0) + ((size_t)b * SLEN + s0) * DMODEL;
    const float* Wn = W + (size_t)n * DMODEL * DHEAD;

    const int m_w = (warp >> 1) << 5;
    const int n_w = (warp & 1) << 5;

    float acc[2][4][4];
#pragma unroll
    for (int mi = 0; mi < 2; mi++)
#pragma unroll
        for (int ni = 0; ni < 4; ni++)
#pragma unroll
            for (int j = 0; j < 4; j++) acc[mi][ni][j] = 0.f;

    for (int k0 = 0; k0 < DMODEL; k0 += 64) {
#pragma unroll
        for (int it = 0; it < 8; it++) {
            int idx = it * 256 + tid;
            int r = idx >> 4, c = (idx & 15) << 2;
            float4 v = *(const float4*)(X + (size_t)r * DMODEL + k0 + c);
            __nv_bfloat16 h, l;
            split2(v.x, h, l); Ah[r * PAD + c + 0] = h; Al[r * PAD + c + 0] = l;
            split2(v.y, h, l); Ah[r * PAD + c + 1] = h; Al[r * PAD + c + 1] = l;
            split2(v.z, h, l); Ah[r * PAD + c + 2] = h; Al[r * PAD + c + 2] = l;
            split2(v.w, h, l); Ah[r * PAD + c + 3] = h; Al[r * PAD + c + 3] = l;
        }
#pragma unroll
        for (int it = 0; it < 4; it++) {
            int idx = it * 256 + tid;
            int r = idx >> 4, c = (idx & 15) << 2;
            float4 v = *(const float4*)(Wn + (size_t)(k0 + r) * DHEAD + c);
            __nv_bfloat16 h, l;
            split2(v.x, h, l); Bh[r * PAD + c + 0] = h; Bl[r * PAD + c + 0] = l;
            split2(v.y, h, l); Bh[r * PAD + c + 1] = h; Bl[r * PAD + c + 1] = l;
            split2(v.z, h, l); Bh[r * PAD + c + 2] = h; Bl[r * PAD + c + 2] = l;
            split2(v.w, h, l); Bh[r * PAD + c + 3] = h; Bl[r * PAD + c + 3] = l;
        }
        __syncthreads();
#pragma unroll
        for (int ks = 0; ks < 64; ks += 16)
            mma_step(Ah, Al, Bh, Bl, ks, m_w, n_w, lane, acc);
        __syncthreads();
    }

#pragma unroll
    for (int mi = 0; mi < 2; mi++) {
        int row = m_w + mi * 16 + (lane >> 2);
#pragma unroll
        for (int ni = 0; ni < 4; ni++) {
            int col = n_w + ni * 8 + ((lane & 3) << 1);
            float b0 = bias[n * DHEAD + col], b1 = bias[n * DHEAD + col + 1];
#pragma unroll
            for (int half = 0; half < 2; half++) {
                float v0 = acc[mi][ni][half * 2 + 0] + b0;
                float v1 = acc[mi][ni][half * 2 + 1] + b1;
                __nv_bfloat16 h0, l0, h1, l1;
                split2(v0, h0, l0); split2(v1, h1, l1);
                size_t o = (((size_t)seq * NHEADS + n) * SLEN + s0 + row + half * 8) * DHEAD + col;
                *(__nv_bfloat162*)(outh + o) = __nv_bfloat162(h0, h1);
                *(__nv_bfloat162*)(outl + o) = __nv_bfloat162(l0, l1);
            }
        }
    }
}

// ---------------------------------------------------------------------------
// Kernel 2: tensor-core causal flash attention.
// grid = (8 q-tiles of 128 [reversed], 96 seq*head), 256 threads (8 warps).
// Each warp owns 16 q-rows. K-tiles of 64 keys streamed through smem.
// K stored [key][head] = n-major = mma col-B layout -> NON-trans ldmatrix.
// V stored [key][head] = k-major -> trans ldmatrix.
// ---------------------------------------------------------------------------
__global__ __launch_bounds__(256) void attn_mma_kernel()
{
    extern __shared__ __nv_bfloat16 sm[];
    __nv_bfloat16* Qh = sm;                    // 128 x PAD
    __nv_bfloat16* Ql = Qh + 128 * PAD;
    __nv_bfloat16* Kh = Ql + 128 * PAD;        // 64 x PAD
    __nv_bfloat16* Kl = Kh + 64 * PAD;
    __nv_bfloat16* Vh = Kl + 64 * PAD;
    __nv_bfloat16* Vl = Vh + 64 * PAD;

    const int tid = threadIdx.x, lane = tid & 31, warp = tid >> 5;
    const int qb  = 7 - blockIdx.x;            // long blocks first
    const int hn  = blockIdx.y;
    const int seq = hn / NHEADS, n = hn - (hn / NHEADS) * NHEADS;

    const size_t hb = ((size_t)seq * NHEADS + n) * SLEN * DHEAD;
    const __nv_bfloat16* gQh = g_Qh + hb + (size_t)qb * 128 * DHEAD;
    const __nv_bfloat16* gQl = g_Ql + hb + (size_t)qb * 128 * DHEAD;

    // load Q tile 128x64 (hi+lo)
#pragma unroll
    for (int it = 0; it < 4; it++) {
        int idx = it * 256 + tid;
        int r = idx >> 3, c8 = (idx & 7) << 3;
        *(uint4*)(Qh + r * PAD + c8) = *(const uint4*)(gQh + r * DHEAD + c8);
        *(uint4*)(Ql + r * PAD + c8) = *(const uint4*)(gQl + r * DHEAD + c8);
    }
    __syncthreads();

    // Q fragments in registers (per warp: rows warp*16..+15, all 64 k-cols)
    uint32_t qfh[4][4], qfl[4][4];
    {
        int ar = warp * 16 + (lane & 15);
        int ac = (lane >> 4) << 3;
#pragma unroll
        for (int ks = 0; ks < 4; ks++) {
            ldsm_x4(qfh[ks], sptr(Qh + ar * PAD + ks * 16 + ac));
            ldsm_x4(qfl[ks], sptr(Ql + ar * PAD + ks * 16 + ac));
        }
    }

    const float SCALE2 = 0.18033688011112042f;  // 0.125 * log2(e)
    float oacc[8][4];
#pragma unroll
    for (int j = 0; j < 8; j++)
#pragma unroll
        for (int e = 0; e < 4; e++) oacc[j][e] = 0.f;
    float mrow[2] = {-1e30f, -1e30f};
    float lrow[2] = {0.f, 0.f};

    const int wrmin = qb * 128 + warp * 16;
    const int wrmax = wrmin + 15;
    const int g0 = wrmin + (lane >> 2);
    const int nkb = 2 * qb + 2;

    // B-fragment (K) ldmatrix addressing: non-trans x4.
    // tile i (lanes 8i..8i+7): keys grp = (lane>>4), k-chunk = (lane>>3)&1
    const int k_row_off = ((lane >> 4) << 3) + (lane & 7);
    const int k_col_off = ((lane >> 3) & 1) << 3;

    for (int kb = 0; kb < nkb; kb++) {
        __syncthreads();
        {
            const size_t kvb = hb + (size_t)kb * 64 * DHEAD;
#pragma unroll
            for (int it = 0; it < 2; it++) {
                int idx = it * 256 + tid;
                int r = idx >> 3, c8 = (idx & 7) << 3;
                size_t gi = kvb + (size_t)r * DHEAD + c8;
                *(uint4*)(Kh + r * PAD + c8) = *(const uint4*)(g_Kh + gi);
                *(uint4*)(Kl + r * PAD + c8) = *(const uint4*)(g_Kl + gi);
                *(uint4*)(Vh + r * PAD + c8) = *(const uint4*)(g_Vh + gi);
                *(uint4*)(Vl + r * PAD + c8) = *(const uint4*)(g_Vl + gi);
            }
        }
        __syncthreads();

        if (kb * 64 > wrmax) continue;   // fully masked for this warp

        // S = Q K^T (3-pass hi/lo)
        float sacc[8][4];
#pragma unroll
        for (int j = 0; j < 8; j++)
#pragma unroll
            for (int e = 0; e < 4; e++) sacc[j][e] = 0.f;

#pragma unroll
        for (int ks = 0; ks < 4; ks++) {
#pragma unroll
            for (int jp = 0; jp < 4; jp++) {
                uint32_t bh[4], bl[4];
                int krow = jp * 16 + k_row_off;
                int kcol = ks * 16 + k_col_off;
                ldsm_x4(bh, sptr(Kh + krow * PAD + kcol));
                ldsm_x4(bl, sptr(Kl + krow * PAD + kcol));
                mma_bf16(sacc[2 * jp + 0], qfh[ks], bh + 0);
                mma_bf16(sacc[2 * jp + 0], qfh[ks], bl + 0);
                mma_bf16(sacc[2 * jp + 0], qfl[ks], bh + 0);
                mma_bf16(sacc[2 * jp + 1], qfh[ks], bh + 2);
                mma_bf16(sacc[2 * jp + 1], qfh[ks], bl + 2);
                mma_bf16(sacc[2 * jp + 1], qfl[ks], bh + 2);
            }
        }

        // scale (+ base-2) and causal mask
        const bool partial = (kb * 64 + 63 > wrmin);
        if (partial) {
#pragma unroll
            for (int j = 0; j < 8; j++)
#pragma unroll
                for (int e = 0; e < 4; e++) {
                    int col = kb * 64 + j * 8 + ((lane & 3) << 1) + (e & 1);
                    int row = g0 + ((e >> 1) << 3);
                    float v = sacc[j][e] * SCALE2;
                    sacc[j][e] = (col > row) ? -1e30f : v;
                }
        } else {
#pragma unroll
            for (int j = 0; j < 8; j++)
#pragma unroll
                for (int e = 0; e < 4; e++) sacc[j][e] *= SCALE2;
        }

        // row max (2 rows per thread), quad reduce
        float mx0 = -1e30f, mx1 = -1e30f;
#pragma unroll
        for (int j = 0; j < 8; j++) {
            mx0 = fmaxf(mx0, fmaxf(sacc[j][0], sacc[j][1]));
            mx1 = fmaxf(mx1, fmaxf(sacc[j][2], sacc[j][3]));
        }
        mx0 = fmaxf(mx0, __shfl_xor_sync(0xffffffffu, mx0, 1));
        mx0 = fmaxf(mx0, __shfl_xor_sync(0xffffffffu, mx0, 2));
        mx1 = fmaxf(mx1, __shfl_xor_sync(0xffffffffu, mx1, 1));
        mx1 = fmaxf(mx1, __shfl_xor_sync(0xffffffffu, mx1, 2));

        float nm0 = fmaxf(mrow[0], mx0), nm1 = fmaxf(mrow[1], mx1);
        float c0 = fast_exp2(mrow[0] - nm0), c1 = fast_exp2(mrow[1] - nm1);
        mrow[0] = nm0; mrow[1] = nm1;
        lrow[0] *= c0; lrow[1] *= c1;
#pragma unroll
        for (int j = 0; j < 8; j++) {
            oacc[j][0] *= c0; oacc[j][1] *= c0;
            oacc[j][2] *= c1; oacc[j][3] *= c1;
        }

        // exp + l accumulation (quad-partial; reduced at end)
#pragma unroll
        for (int j = 0; j < 8; j++) {
            float p0 = fast_exp2(sacc[j][0] - nm0);
            float p1 = fast_exp2(sacc[j][1] - nm0);
            float p2 = fast_exp2(sacc[j][2] - nm1);
            float p3 = fast_exp2(sacc[j][3] - nm1);
            sacc[j][0] = p0; sacc[j][1] = p1; sacc[j][2] = p2; sacc[j][3] = p3;
            lrow[0] += p0 + p1; lrow[1] += p2 + p3;
        }

        // PV: O += P V (P hi/lo from registers, V hi/lo from smem, trans loads)
#pragma unroll
        for (int kk = 0; kk < 4; kk++) {
            uint32_t ph[4], pl[4];
            {
                float* s0p = sacc[2 * kk];
                float* s1p = sacc[2 * kk + 1];
                float h00 = __bfloat162float(__float2bfloat16(s0p[0]));
                float h01 = __bfloat162float(__float2bfloat16(s0p[1]));
                float h02 = __bfloat162float(__float2bfloat16(s0p[2]));
                float h03 = __bfloat162float(__float2bfloat16(s0p[3]));
                float h10 = __bfloat162float(__float2bfloat16(s1p[0]));
                float h11 = __bfloat162float(__float2bfloat16(s1p[1]));
                float h12 = __bfloat162float(__float2bfloat16(s1p[2]));
                float h13 = __bfloat162float(__float2bfloat16(s1p[3]));
                ph[0] = packbf(h00, h01);   ph[1] = packbf(h02, h03);
                ph[2] = packbf(h10, h11);   ph[3] = packbf(h12, h13);
                pl[0] = packbf(s0p[0] - h00, s0p[1] - h01);
                pl[1] = packbf(s0p[2] - h02, s0p[3] - h03);
                pl[2] = packbf(s1p[0] - h10, s1p[1] - h11);
                pl[3] = packbf(s1p[2] - h12, s1p[3] - h13);
            }
            int br = kk * 16 + (lane & 15);
            int bc = (lane >> 4) << 3;
#pragma unroll
            for (int jp = 0; jp < 4; jp++) {
                uint32_t bvh[4], bvl[4];
                ldsm_x4t(bvh, sptr(Vh + br * PAD + jp * 16 + bc));
                ldsm_x4t(bvl, sptr(Vl + br * PAD + jp * 16 + bc));
                mma_bf16(oacc[2 * jp + 0], ph, bvh + 0);
                mma_bf16(oacc[2 * jp + 0], ph, bvl + 0);
                mma_bf16(oacc[2 * jp + 0], pl, bvh + 0);
                mma_bf16(oacc[2 * jp + 1], ph, bvh + 2);
                mma_bf16(oacc[2 * jp + 1], ph, bvl + 2);
                mma_bf16(oacc[2 * jp + 1], pl, bvh + 2);
            }
        }
    }

    // final reduce l across quad, normalize, write Z
    lrow[0] += __shfl_xor_sync(0xffffffffu, lrow[0], 1);
    lrow[0] += __shfl_xor_sync(0xffffffffu, lrow[0], 2);
    lrow[1] += __shfl_xor_sync(0xffffffffu, lrow[1], 1);
    lrow[1] += __shfl_xor_sync(0xffffffffu, lrow[1], 2);
    float inv0 = 1.f / lrow[0], inv1 = 1.f / lrow[1];

    const int s_row0 = qb * 128 + warp * 16 + (lane >> 2);
#pragma unroll
    for (int j = 0; j < 8; j++) {
        int col = n * DHEAD + j * 8 + ((lane & 3) << 1);
        size_t z0 = ((size_t)seq * SLEN + s_row0) * DMODEL + col;
        *(float2*)(g_Z + z0) = make_float2(oacc[j][0] * inv0, oacc[j][1] * inv0);
        *(float2*)(g_Z + z0 + (size_t)8 * DMODEL) = make_float2(oacc[j][2] * inv1, oacc[j][3] * inv1);
    }
}

// ---------------------------------------------------------------------------
// Kernel 3a: out[:, 0:2] = Z @ W_O_flat(768x768) + b_O
// ---------------------------------------------------------------------------
__global__ __launch_bounds__(256) void out01_mma_kernel(
    const float* __restrict__ WO, const float* __restrict__ bO,
    float* __restrict__ out)
{
    extern __shared__ __nv_bfloat16 smem[];
    __nv_bfloat16* Ah = smem;
    __nv_bfloat16* Al = Ah + 128 * PAD;
    __nv_bfloat16* Bh = Al + 128 * PAD;
    __nv_bfloat16* Bl = Bh + 64 * PAD;

    const int tid = threadIdx.x, lane = tid & 31, warp = tid >> 5;
    const int r0g = blockIdx.x << 7;
    const int c0g = blockIdx.y << 6;
    const float* A = g_Z + (size_t)r0g * DMODEL;

    const int m_w = (warp >> 1) << 5;
    const int n_w = (warp & 1) << 5;

    float acc[2][4][4];
#pragma unroll
    for (int mi = 0; mi < 2; mi++)
#pragma unroll
        for (int ni = 0; ni < 4; ni++)
#pragma unroll
            for (int j = 0; j < 4; j++) acc[mi][ni][j] = 0.f;

    for (int k0 = 0; k0 < DMODEL; k0 += 64) {
#pragma unroll
        for (int it = 0; it < 8; it++) {
            int idx = it * 256 + tid;
            int r = idx >> 4, c = (idx & 15) << 2;
            float4 v = *(const float4*)(A + (size_t)r * DMODEL + k0 + c);
            __nv_bfloat16 h, l;
            split2(v.x, h, l); Ah[r * PAD + c + 0] = h; Al[r * PAD + c + 0] = l;
            split2(v.y, h, l); Ah[r * PAD + c + 1] = h; Al[r * PAD + c + 1] = l;
            split2(v.z, h, l); Ah[r * PAD + c + 2] = h; Al[r * PAD + c + 2] = l;
            split2(v.w, h, l); Ah[r * PAD + c + 3] = h; Al[r * PAD + c + 3] = l;
        }
#pragma unroll
        for (int it = 0; it < 4; it++) {
            int idx = it * 256 + tid;
            int r = idx >> 4, c = (idx & 15) << 2;
            float4 v = *(const float4*)(WO + (size_t)(k0 + r) * DMODEL + c0g + c);
            __nv_bfloat16 h, l;
            split2(v.x, h, l); Bh[r * PAD + c + 0] = h; Bl[r * PAD + c + 0] = l;
            split2(v.y, h, l); Bh[r * PAD + c + 1] = h; Bl[r * PAD + c + 1] = l;
            split2(v.z, h, l); Bh[r * PAD + c + 2] = h; Bl[r * PAD + c + 2] = l;
            split2(v.w, h, l); Bh[r * PAD + c + 3] = h; Bl[r * PAD + c + 3] = l;
        }
        __syncthreads();
#pragma unroll
        for (int ks = 0; ks < 64; ks += 16)
            mma_step(Ah, Al, Bh, Bl, ks, m_w, n_w, lane, acc);
        __syncthreads();
    }

#pragma unroll
    for (int mi = 0; mi < 2; mi++) {
        int rloc = m_w + mi * 16 + (lane >> 2);
#pragma unroll
        for (int ni = 0; ni < 4; ni++) {
            int col = n_w + ni * 8 + ((lane & 3) << 1);
            float b0 = bO[c0g + col], b1 = bO[c0g + col + 1];
#pragma unroll
            for (int half = 0; half < 2; half++) {
                int r = r0g + rloc + half * 8;
                int seq = r >> 10, s = r & 1023;
                int b = seq >> 1, p = seq & 1;
                size_t oidx = (((size_t)(b * 14 + p)) * SLEN + s) * DMODEL + c0g + col;
                float2 v = make_float2(acc[mi][ni][half * 2 + 0] + b0,
                                       acc[mi][ni][half * 2 + 1] + b1);
                *(float2*)(out + oidx) = v;
            }
        }
    }
}

// ---------------------------------------------------------------------------
// Kernel 3b: out[:, 2+k] = out[:, 1] + (Z_alt_k - Z_orig_k) @ W_O[k]
// ---------------------------------------------------------------------------
__global__ __launch_bounds__(256) void ablate_mma_kernel(
    const float* __restrict__ WO, float* __restrict__ out)
{
    extern __shared__ __nv_bfloat16 smem[];
    __nv_bfloat16* Ah = smem;
    __nv_bfloat16* Al = Ah + 128 * PAD;
    __nv_bfloat16* Bh = Al + 128 * PAD;
    __nv_bfloat16* Bl = Bh + 64 * PAD;

    const int tid = threadIdx.x, lane = tid & 31, warp = tid >> 5;
    const int k  = blockIdx.z;
    const int t0 = blockIdx.y << 7;
    const int d0 = blockIdx.x << 6;
    const int b  = t0 >> 10;
    const int s0 = t0 & 1023;

    const float* Za = g_Z + ((size_t)(b * 2 + 0) * SLEN + s0) * DMODEL + k * DHEAD;
    const float* Zo = g_Z + ((size_t)(b * 2 + 1) * SLEN + s0) * DMODEL + k * DHEAD;
    const float* Wk = WO + (size_t)k * DHEAD * DMODEL + d0;

#pragma unroll
    for (int it = 0; it < 8; it++) {
        int idx = it * 256 + tid;
        int r = idx >> 4, c = (idx & 15) << 2;
        float4 a = *(const float4*)(Za + (size_t)r * DMODEL + c);
        float4 q = *(const float4*)(Zo + (size_t)r * DMODEL + c);
        float d[4] = {a.x - q.x, a.y - q.y, a.z - q.z, a.w - q.w};
        __nv_bfloat16 h, l;
#pragma unroll
        for (int j = 0; j < 4; j++) {
            split2(d[j], h, l);
            Ah[r * PAD + c + j] = h; Al[r * PAD + c + j] = l;
        }
    }
#pragma unroll
    for (int it = 0; it < 4; it++) {
        int idx = it * 256 + tid;
        int r = idx >> 4, c = (idx & 15) << 2;
        float4 v = *(const float4*)(Wk + (size_t)r * DMODEL + c);
        __nv_bfloat16 h, l;
        split2(v.x, h, l); Bh[r * PAD + c + 0] = h; Bl[r * PAD + c + 0] = l;
        split2(v.y, h, l); Bh[r * PAD + c + 1] = h; Bl[r * PAD + c + 1] = l;
        split2(v.z, h, l); Bh[r * PAD + c + 2] = h; Bl[r * PAD + c + 2] = l;
        split2(v.w, h, l); Bh[r * PAD + c + 3] = h; Bl[r * PAD + c + 3] = l;
    }
    __syncthreads();

    const int m_w = (warp >> 1) << 5;
    const int n_w = (warp & 1) << 5;

    float acc[2][4][4];
#pragma unroll
    for (int mi = 0; mi < 2; mi++)
#pragma unroll
        for (int ni = 0; ni < 4; ni++)
#pragma unroll
            for (int j = 0; j < 4; j++) acc[mi][ni][j] = 0.f;

#pragma unroll
    for (int ks = 0; ks < 64; ks += 16)
        mma_step(Ah, Al, Bh, Bl, ks, m_w, n_w, lane, acc);

#pragma unroll
    for (int mi = 0; mi < 2; mi++) {
        int rloc = m_w + mi * 16 + (lane >> 2);
#pragma unroll
        for (int ni = 0; ni < 4; ni++) {
            int col = n_w + ni * 8 + ((lane & 3) << 1);
#pragma unroll
            for (int half = 0; half < 2; half++) {
                int s = s0 + rloc + half * 8;
                size_t base1 = (((size_t)(b * 14 + 1)) * SLEN + s) * DMODEL + d0 + col;
                size_t basek = (((size_t)(b * 14 + 2 + k)) * SLEN + s) * DMODEL + d0 + col;
                float2 base = *(const float2*)(out + base1);
                float2 v = make_float2(acc[mi][ni][half * 2 + 0] + base.x,
                                       acc[mi][ni][half * 2 + 1] + base.y);
                *(float2*)(out + basek) = v;
            }
        }
    }
}

// ---------------------------------------------------------------------------

extern "C" void kernel_launch(void* const* d_in, const int* in_sizes, int n_in,
                              void* d_out, int out_size)
{
    const float* x0 = (const float*)d_in[0];
    const float* x1 = (const float*)d_in[1];
    const float* WQ = (const float*)d_in[2];
    const float* bQ = (const float*)d_in[3];
    const float* WK = (const float*)d_in[4];
    const float* bK = (const float*)d_in[5];
    const float* WV = (const float*)d_in[6];
    const float* bV = (const float*)d_in[7];
    const float* WO = (const float*)d_in[8];
    const float* bO = (const float*)d_in[9];
    float* out = (float*)d_out;

    const int gemm_smem = (128 * 2 + 64 * 2) * PAD * (int)sizeof(__nv_bfloat16);
    cudaFuncSetAttribute(qkv_mma_kernel, cudaFuncAttributeMaxDynamicSharedMemorySize, gemm_smem);
    cudaFuncSetAttribute(out01_mma_kernel, cudaFuncAttributeMaxDynamicSharedMemorySize, gemm_smem);
    cudaFuncSetAttribute(ablate_mma_kernel, cudaFuncAttributeMaxDynamicSharedMemorySize, gemm_smem);

    const int attn_smem = (128 * 2 + 64 * 4) * PAD * (int)sizeof(__nv_bfloat16); // 73728
    cudaFuncSetAttribute(attn_mma_kernel, cudaFuncAttributeMaxDynamicSharedMemorySize, attn_smem);

    qkv_mma_kernel<<<dim3(64, 36), 256, gemm_smem>>>(x0, x1, WQ, bQ, WK, bK, WV, bV);
    attn_mma_kernel<<<dim3(8, 96), 256, attn_smem>>>();
    out01_mma_kernel<<<dim3(64, 12), 256, gemm_smem>>>(WO, bO, out);
    ablate_mma_kernel<<<dim3(12, 32, 12), 256, gemm_smem>>>(WO, out);
}